// round 3
// baseline (speedup 1.0000x reference)
#include <cuda_runtime.h>
#include <cstdint>
#include <cstddef>
typedef unsigned long long ull;
#define C3 384

__device__ float g_xw[(size_t)1024 * 256 * C3];     // [t][b][384] gate pre-acts
__device__ float g_seq1[(size_t)1024 * 256 * 128];  // [t][b][128] layer-1 outputs

__device__ __forceinline__ ull ffma2(ull a, ull b, ull c) {
    ull d; asm("fma.rn.f32x2 %0,%1,%2,%3;" : "=l"(d) : "l"(a), "l"(b), "l"(c)); return d;
}
__device__ __forceinline__ ull pack2(float x, float y) {
    ull d; asm("mov.b64 %0,{%1,%2};" : "=l"(d) : "f"(x), "f"(y)); return d;
}
__device__ __forceinline__ float2 up2(ull v) {
    float x, y; asm("mov.b64 {%0,%1},%2;" : "=f"(x), "=f"(y) : "l"(v)); return make_float2(x, y);
}

// out-row[t*256+b][c] = sum_k in[row][k]*W[k][c] + bias[c]
template<int K, bool L1>
__global__ void __launch_bounds__(384, 1) k_xw(const float* __restrict__ in,
                                               const float* __restrict__ W,
                                               const float* __restrict__ bias) {
    __shared__ __align__(16) float xs[32 * K];
    int c = threadIdx.x;
    float bc = bias[c];
    for (int ch = blockIdx.x; ch < 8192; ch += gridDim.x) {
        int r0 = ch * 32;
        const float4* src = (const float4*)((L1 ? in : (const float*)g_seq1) + (size_t)r0 * K);
        __syncthreads();
        for (int i = c; i < 32 * K / 4; i += 384) ((float4*)xs)[i] = src[i];
        __syncthreads();
        ull acc[32];
#pragma unroll
        for (int r = 0; r < 32; r++) acc[r] = 0ull;
        for (int kq = 0; kq < K / 4; kq++) {
            const float* wp = W + (size_t)(4 * kq) * C3 + c;
            ull wA = pack2(wp[0], wp[C3]);
            ull wB = pack2(wp[2 * C3], wp[3 * C3]);
#pragma unroll
            for (int r = 0; r < 32; r++) {
                ulonglong2 x4 = *(const ulonglong2*)&xs[r * K + 4 * kq];
                acc[r] = ffma2(x4.x, wA, acc[r]);
                acc[r] = ffma2(x4.y, wB, acc[r]);
            }
        }
#pragma unroll
        for (int r = 0; r < 32; r++) {
            float2 v = up2(acc[r]);
            int rr = r0 + r;
            int orow = L1 ? ((rr & 1023) * 256 + (rr >> 10)) : rr;  // [b][t] -> [t][b]
            g_xw[(size_t)orow * C3 + c] = v.x + v.y + bc;
        }
    }
}

// Sequential GRU: 1 CTA = 2 batch rows; 384 threads = 384 gate columns.
// Recurrent weights in registers (64 packed k-pairs per thread).
template<bool WSEQ>
__global__ void __launch_bounds__(384, 1) k_gru(const float* __restrict__ Uw,
                                                const float* __restrict__ br,
                                                float* __restrict__ stateOut,
                                                float* __restrict__ xOut) {
    __shared__ __align__(16) float hs[2][128];
    __shared__ float r0s[C3], r1s[C3];
    int c = threadIdx.x, p = blockIdx.x;
    ull wp[64];
#pragma unroll
    for (int j = 0; j < 64; j++)
        wp[j] = pack2(Uw[(size_t)(2 * j) * C3 + c], Uw[(size_t)(2 * j + 1) * C3 + c]);
    float brc = br[c];
    if (c < 128) { hs[0][c] = 0.f; hs[1][c] = 0.f; }
    int u = c & 127, bl = (c >> 7) & 1;
    bool g = c < 256;
    int b = 2 * p + bl;
    const float* xq = g_xw + (size_t)b * C3 + u;
    float* sq = g_seq1 + (size_t)b * 128 + u;
    __syncthreads();
    for (int t = 0; t < 1024; t++) {
        float xz = 0.f, xr = 0.f, xh = 0.f;
        if (g) {  // prefetch this step's input projections (hidden under the dot)
            const float* q = xq + (size_t)t * (256 * C3);
            xz = q[0]; xr = q[128]; xh = q[256];
        }
        ull a0 = 0ull, a1 = 0ull;
#pragma unroll
        for (int i = 0; i < 32; i++) {
            ulonglong2 h0 = *(const ulonglong2*)&hs[0][4 * i];
            ulonglong2 h1 = *(const ulonglong2*)&hs[1][4 * i];
            a0 = ffma2(h0.x, wp[2 * i], a0);
            a0 = ffma2(h0.y, wp[2 * i + 1], a0);
            a1 = ffma2(h1.x, wp[2 * i], a1);
            a1 = ffma2(h1.y, wp[2 * i + 1], a1);
        }
        { float2 v = up2(a0); r0s[c] = v.x + v.y + brc; }
        { float2 v = up2(a1); r1s[c] = v.x + v.y + brc; }
        __syncthreads();
        if (g) {
            const float* rs = bl ? r1s : r0s;
            float z  = 1.f / (1.f + expf(-(xz + rs[u])));
            float r  = 1.f / (1.f + expf(-(xr + rs[u + 128])));
            float hh = fmaxf(xh + r * rs[u + 256], 0.f);
            float hn = z * hs[bl][u] + (1.f - z) * hh;
            hs[bl][u] = hn;
            if (WSEQ) sq[(size_t)t * (256 * 128)] = hn;
            if (t == 1023) {
                stateOut[(size_t)b * 128 + u] = hn;
                if (xOut) xOut[(size_t)b * 128 + u] = hn;
            }
        }
        __syncthreads();
    }
}

extern "C" void kernel_launch(void* const* d_in, const int* in_sizes, int n_in,
                              void* d_out, int out_size) {
    const float* x  = (const float*)d_in[0];
    const float* W1 = (const float*)d_in[1];
    const float* U1 = (const float*)d_in[2];
    const float* b1 = (const float*)d_in[3];
    const float* W2 = (const float*)d_in[4];
    const float* U2 = (const float*)d_in[5];
    const float* b2 = (const float*)d_in[6];
    float* out = (float*)d_out;  // [x | state1 | state2], each 256*128
    k_xw<64, true><<<148, 384>>>(x, W1, b1);
    k_gru<true><<<128, 384>>>(U1, b1 + C3, out + 32768, nullptr);
    k_xw<128, false><<<148, 384>>>(nullptr, W2, b2);
    k_gru<false><<<128, 384>>>(U2, b2 + C3, out + 65536, out);
}